// round 14
// baseline (speedup 1.0000x reference)
#include <cuda_runtime.h>
#include <cuda.h>

// Router: logits = x @ wg^T + gr @ gm^T ; std-normalized softmax; top-2;
// mask expert E-1; renormalize.
// Output layout (float32): [gates 2T | indices 2T | logits 8T]
//
// R14: TMA. R7-R13 plateau diagnosis: LDGSTS fill (32cy/2KB) + LDS reads
// (32cy/2KB) both go through L1tex -> ~16.5us of L1 work that serializes
// with the ~16.7us DRAM epoch => ~33us. TMA (cp.async.bulk.tensor.2d)
// fills smem via the tma pipe with ZERO LSU instructions; L1 work drops
// to ~9.4us << DRAM floor. CTA = 128 contiguous tokens, 16 warps, warp
// owns 8 tokens (octet-expert split, acc = 32 regs). Stage = 128 tok x
// 32 floats = 16KB; 64 stages; DEPTH=6 ring + full/empty mbarriers.

constexpr int D        = 2048;
constexpr int E        = 8;
constexpr int TB       = 128;               // tokens per CTA
constexpr int THREADS  = 512;               // 16 warps
constexpr int NT       = 8;                 // tokens per warp
constexpr int CHUNKS   = D / 4;             // 512 16B-chunks per row
constexpr int STAGE_CH = 8;                 // chunks per token per stage (128B)
constexpr int STAGES   = CHUNKS / STAGE_CH; // 64
constexpr int DEPTH    = 6;
constexpr int STAGE_BYTES = TB * STAGE_CH * 16;   // 16384

// smem floats: wg[16384] | gm[64] | ring[DEPTH*4096] | mbars
constexpr int WG_F       = E * D;                       // 16384
constexpr int RING_OFF_F = WG_F + 64;                   // 16448
constexpr int RING_F     = DEPTH * (STAGE_BYTES / 4);   // 24576
constexpr int MBAR_OFF_F = RING_OFF_F + RING_F;         // 41024
constexpr int SMEM_BYTES = MBAR_OFF_F * 4 + 2 * DEPTH * 8 + 16;

__device__ __forceinline__ unsigned long long ffma2(unsigned long long a,
                                                    unsigned long long b,
                                                    unsigned long long c) {
    unsigned long long d;
    asm("fma.rn.f32x2 %0, %1, %2, %3;" : "=l"(d) : "l"(a), "l"(b), "l"(c));
    return d;
}

__device__ __forceinline__ float pairsum(unsigned long long v) {
    float2 f;
    f.x = __uint_as_float((unsigned int)(v & 0xffffffffull));
    f.y = __uint_as_float((unsigned int)(v >> 32));
    return f.x + f.y;
}

__device__ __forceinline__ void mbar_init(unsigned int a, unsigned int cnt) {
    asm volatile("mbarrier.init.shared.b64 [%0], %1;" :: "r"(a), "r"(cnt) : "memory");
}
__device__ __forceinline__ void mbar_arrive(unsigned int a) {
    asm volatile("mbarrier.arrive.shared.b64 _, [%0];" :: "r"(a) : "memory");
}
__device__ __forceinline__ void mbar_expect_tx(unsigned int a, unsigned int tx) {
    asm volatile("mbarrier.arrive.expect_tx.shared.b64 _, [%0], %1;"
                 :: "r"(a), "r"(tx) : "memory");
}
__device__ __forceinline__ void mbar_wait(unsigned int a, unsigned int parity) {
    asm volatile(
        "{\n\t.reg .pred P;\n\t"
        "WL_%=:\n\t"
        "mbarrier.try_wait.parity.acquire.cta.shared::cta.b64 P, [%0], %1, 0x989680;\n\t"
        "@P bra.uni WD_%=;\n\t"
        "bra.uni WL_%=;\n\t"
        "WD_%=:\n\t}"
        :: "r"(a), "r"(parity) : "memory");
}
__device__ __forceinline__ void tma2d(unsigned int dst, const CUtensorMap* m,
                                      int cx, int cy, unsigned int mbar) {
    asm volatile(
        "cp.async.bulk.tensor.2d.shared::cta.global.tile.mbarrier::complete_tx::bytes "
        "[%0], [%1, {%2, %3}], [%4];"
        :: "r"(dst), "l"(m), "r"(cx), "r"(cy), "r"(mbar) : "memory");
}

__global__ void __launch_bounds__(THREADS, 1)
router_kernel(const __grid_constant__ CUtensorMap tmx,
              const float* __restrict__ wg,
              const float* __restrict__ gm,
              const float* __restrict__ gr,
              float* __restrict__ out_gates,
              float* __restrict__ out_idx,
              float* __restrict__ out_logits) {
    extern __shared__ float smem[];
    float4* s_wg4 = reinterpret_cast<float4*>(smem);
    float*  s_gm  = smem + WG_F;

    const int tid  = threadIdx.x;
    const int lane = tid & 31;
    const int wid  = tid >> 5;
    const int l8   = lane & 7;
    const int e0   = (lane >> 3) * 2;

    // stage wg + gm
    const float4* wg4 = reinterpret_cast<const float4*>(wg);
    for (int i = tid; i < E * CHUNKS; i += THREADS) s_wg4[i] = wg4[i];
    if (tid < E * E) s_gm[tid] = gm[tid];

    const unsigned int smem_u32 =
        (unsigned int)__cvta_generic_to_shared(smem);
    const unsigned int ring_u32 = smem_u32 + RING_OFF_F * 4;
    const unsigned int mb       = smem_u32 + MBAR_OFF_F * 4;
    // full[s] = mb + s*8 ; empty[s] = mb + DEPTH*8 + s*8

    if (tid == 0) {
        #pragma unroll
        for (int s = 0; s < DEPTH; s++) {
            mbar_init(mb + s * 8, 1);                       // full
            mbar_init(mb + DEPTH * 8 + s * 8, THREADS);     // empty
        }
        asm volatile("fence.proxy.async.shared::cta;" ::: "memory");
    }
    __syncthreads();

    const int tokBase = blockIdx.x * TB;

    // prologue: fill slots 0..DEPTH-1
    if (tid == 0) {
        #pragma unroll
        for (int s = 0; s < DEPTH; s++) {
            mbar_expect_tx(mb + s * 8, STAGE_BYTES);
            tma2d(ring_u32 + s * STAGE_BYTES, &tmx,
                  s * (STAGE_CH * 4), tokBase, mb + s * 8);
        }
    }

    const ulonglong2* s_w2 = reinterpret_cast<const ulonglong2*>(smem);
    const ulonglong2* ring2 =
        reinterpret_cast<const ulonglong2*>(smem + RING_OFF_F);

    unsigned long long acc[NT][2];
    #pragma unroll
    for (int j = 0; j < NT; j++) { acc[j][0] = 0ull; acc[j][1] = 0ull; }

    int cslot = 0, cphase = 0;
    #pragma unroll 2
    for (int hh = 0; hh < STAGES; hh++) {
        mbar_wait(mb + cslot * 8, cphase);      // full[cslot]

        const ulonglong2* xs = ring2 + cslot * (STAGE_BYTES / 16)
                                     + wid * (NT * STAGE_CH);
        const int c = hh * STAGE_CH + l8;
        ulonglong2 wv0 = s_w2[e0 * CHUNKS + c];
        ulonglong2 wv1 = s_w2[(e0 + 1) * CHUNKS + c];
        #pragma unroll
        for (int j = 0; j < NT; j++) {
            ulonglong2 xv = xs[j * STAGE_CH + l8];
            acc[j][0] = ffma2(xv.x, wv0.x, acc[j][0]);
            acc[j][0] = ffma2(xv.y, wv0.y, acc[j][0]);
            acc[j][1] = ffma2(xv.x, wv1.x, acc[j][1]);
            acc[j][1] = ffma2(xv.y, wv1.y, acc[j][1]);
        }

        mbar_arrive(mb + DEPTH * 8 + cslot * 8);   // empty[cslot], all threads

        if (tid == 0 && hh + DEPTH < STAGES) {
            // wait for all 512 arrives of stage hh, then refill this slot
            mbar_wait(mb + DEPTH * 8 + cslot * 8, cphase);
            mbar_expect_tx(mb + cslot * 8, STAGE_BYTES);
            tma2d(ring_u32 + cslot * STAGE_BYTES, &tmx,
                  (hh + DEPTH) * (STAGE_CH * 4), tokBase, mb + cslot * 8);
        }

        if (++cslot == DEPTH) { cslot = 0; cphase ^= 1; }
    }

    // ---- reduce within each octet (3-step butterfly) ----
    float red[NT][2];
    #pragma unroll
    for (int j = 0; j < NT; j++) {
        #pragma unroll
        for (int e = 0; e < 2; e++) {
            float s = pairsum(acc[j][e]);
            s += __shfl_xor_sync(0xffffffffu, s, 4);
            s += __shfl_xor_sync(0xffffffffu, s, 2);
            s += __shfl_xor_sync(0xffffffffu, s, 1);
            red[j][e] = s;
        }
    }

    // lane (octet q, l8=j) keeps token (base + j)'s logits for experts
    // 2q, 2q+1; gather all 8 experts onto lanes 0-7.
    float s0 = red[0][0], s1 = red[0][1];
    #pragma unroll
    for (int jj = 1; jj < NT; jj++)
        if (l8 == jj) { s0 = red[jj][0]; s1 = red[jj][1]; }

    float logit[E];
    logit[0] = s0;
    logit[1] = s1;
    logit[2] = __shfl_sync(0xffffffffu, s0, l8 + 8);
    logit[3] = __shfl_sync(0xffffffffu, s1, l8 + 8);
    logit[4] = __shfl_sync(0xffffffffu, s0, l8 + 16);
    logit[5] = __shfl_sync(0xffffffffu, s1, l8 + 16);
    logit[6] = __shfl_sync(0xffffffffu, s0, l8 + 24);
    logit[7] = __shfl_sync(0xffffffffu, s1, l8 + 24);

    if (lane < NT) {
        const int t = tokBase + wid * NT + lane;

        float4 g0 = __ldg(reinterpret_cast<const float4*>(gr + (size_t)t * E));
        float4 g1 = __ldg(reinterpret_cast<const float4*>(gr + (size_t)t * E + 4));
        float grv[8] = {g0.x, g0.y, g0.z, g0.w, g1.x, g1.y, g1.z, g1.w};
        float lg[E];
        #pragma unroll
        for (int f = 0; f < E; f++) {
            float s = logit[f];
            #pragma unroll
            for (int e = 0; e < E; e++) s = fmaf(grv[e], s_gm[f * E + e], s);
            lg[f] = s;
        }

        // unbiased std (ddof=1) over E=8
        float mean = 0.f;
        #pragma unroll
        for (int f = 0; f < E; f++) mean += lg[f];
        mean *= (1.f / E);
        float var = 0.f;
        #pragma unroll
        for (int f = 0; f < E; f++) {
            float d = lg[f] - mean;
            var = fmaf(d, d, var);
        }
        float inv_std = rsqrtf(var * (1.f / (E - 1)));

        float z[E], m = -3.402823466e+38f;
        #pragma unroll
        for (int f = 0; f < E; f++) {
            z[f] = lg[f] * inv_std;
            m = fmaxf(m, z[f]);
        }
        float p[E], psum = 0.f;
        #pragma unroll
        for (int f = 0; f < E; f++) {
            p[f] = __expf(z[f] - m);
            psum += p[f];
        }
        float inv_psum = 1.f / psum;
        #pragma unroll
        for (int f = 0; f < E; f++) p[f] *= inv_psum;

        // stable top-2 (descending, lower index wins ties)
        int i1 = 0; float v1 = p[0];
        #pragma unroll
        for (int f = 1; f < E; f++)
            if (p[f] > v1) { v1 = p[f]; i1 = f; }
        int i2; float v2;
        if (i1 == 0) { i2 = 1; v2 = p[1]; } else { i2 = 0; v2 = p[0]; }
        #pragma unroll
        for (int f = 1; f < E; f++)
            if (f != i1 && p[f] > v2) { v2 = p[f]; i2 = f; }

        float gg1 = (i1 == E - 1) ? 0.f : v1;
        float gg2 = (i2 == E - 1) ? 0.f : v2;
        float inv_s = 1.f / (gg1 + gg2);
        gg1 *= inv_s; gg2 *= inv_s;

        float2 gpair; gpair.x = gg1; gpair.y = gg2;
        *reinterpret_cast<float2*>(out_gates + (size_t)2 * t) = gpair;
        float2 ipair; ipair.x = (float)i1; ipair.y = (float)i2;
        *reinterpret_cast<float2*>(out_idx + (size_t)2 * t) = ipair;

        float4 L0; L0.x = lg[0]; L0.y = lg[1]; L0.z = lg[2]; L0.w = lg[3];
        float4 L1; L1.x = lg[4]; L1.y = lg[5]; L1.z = lg[6]; L1.w = lg[7];
        float4* olr = reinterpret_cast<float4*>(out_logits + (size_t)t * E);
        olr[0] = L0;
        olr[1] = L1;
    }
}

typedef CUresult (*PFN_tmeTiled)(
    CUtensorMap*, CUtensorMapDataType, cuuint32_t, void*,
    const cuuint64_t*, const cuuint64_t*, const cuuint32_t*,
    const cuuint32_t*, CUtensorMapInterleave, CUtensorMapSwizzle,
    CUtensorMapL2promotion, CUtensorMapFloatOOBfill);

extern "C" void kernel_launch(void* const* d_in, const int* in_sizes, int n_in,
                              void* d_out, int out_size) {
    const float* x  = (const float*)d_in[0];   // [T, D]
    const float* wg = (const float*)d_in[1];   // [E, D]
    const float* gm = (const float*)d_in[2];   // [E, E]
    const float* gr = (const float*)d_in[3];   // [T, E]

    const int T = in_sizes[0] / D;             // 16384
    float* out       = (float*)d_out;
    float* out_gates = out;                       // [T,2]
    float* out_idx   = out + (size_t)2 * T;       // [T,2] as float
    float* out_logit = out + (size_t)4 * T;       // [T,8]

    // driver entry point via runtime (no -lcuda needed)
    PFN_tmeTiled encode = nullptr;
    cudaDriverEntryPointQueryResult qr;
    cudaGetDriverEntryPointByVersion("cuTensorMapEncodeTiled",
                                     (void**)&encode, 12000,
                                     cudaEnableDefault, &qr);

    CUtensorMap tmx;
    cuuint64_t gdim[2] = {(cuuint64_t)D, (cuuint64_t)T};
    cuuint64_t gstr[1] = {(cuuint64_t)D * 4};
    cuuint32_t box[2]  = {STAGE_CH * 4, TB};      // 32 floats x 128 rows
    cuuint32_t estr[2] = {1, 1};
    encode(&tmx, CU_TENSOR_MAP_DATA_TYPE_FLOAT32, 2, (void*)x,
           gdim, gstr, box, estr,
           CU_TENSOR_MAP_INTERLEAVE_NONE, CU_TENSOR_MAP_SWIZZLE_NONE,
           CU_TENSOR_MAP_L2_PROMOTION_L2_128B,
           CU_TENSOR_MAP_FLOAT_OOB_FILL_NONE);

    cudaFuncSetAttribute(router_kernel,
                         cudaFuncAttributeMaxDynamicSharedMemorySize,
                         SMEM_BYTES);

    router_kernel<<<T / TB, THREADS, SMEM_BYTES>>>(
        tmx, wg, gm, gr, out_gates, out_idx, out_logit);
}